// round 4
// baseline (speedup 1.0000x reference)
#include <cuda_runtime.h>
#include <cstdint>

// ---------------------------------------------------------------------------
// Problem constants: B=64, M=1024, D=1024, H=8, HD=128, M1=64, ALPHA=1.3, EPS=1e-5
// ---------------------------------------------------------------------------

#define N_ROWS   65536        // B*M
#define D_DIM    1024
#define EPS_F    1e-5f

// Scratch (device globals; no allocation allowed)
__device__ float g_v2[67108864];      // (B*M, 1024) v2 after celu+GN  (256 MB)
__device__ float g_qgn[65536];        // (64, 1024)  q after GN
__device__ float g_v1gn[65536];       // (64, 1024)  v1 after GN
__device__ float g_qv1pre[131072];    // (2, 64, 1024) pre-activation partials
__device__ float g_logits[524288];    // (B, H, M)
__device__ float g_ampool[32768];     // (B, H, 64)

// ---------------------------------------------------------------------------
// helpers
// ---------------------------------------------------------------------------
__device__ __forceinline__ float celu_f(float x) {
    return x > 0.f ? x : 1.3f * expm1f(x * (1.0f / 1.3f));
}

__device__ __forceinline__ uint64_t pack2(float lo, float hi) {
    uint64_t r;
    asm("mov.b64 %0, {%1, %2};" : "=l"(r) : "f"(lo), "f"(hi));
    return r;
}
__device__ __forceinline__ void unpack2(uint64_t v, float& lo, float& hi) {
    asm("mov.b64 {%0, %1}, %2;" : "=f"(lo), "=f"(hi) : "l"(v));
}
__device__ __forceinline__ uint64_t ffma2(uint64_t a, uint64_t b, uint64_t c) {
    uint64_t d;
    asm("fma.rn.f32x2 %0, %1, %2, %3;" : "=l"(d) : "l"(a), "l"(b), "l"(c));
    return d;
}

// ---------------------------------------------------------------------------
// zero scratch accumulators (must run every launch; graph is replayed)
// ---------------------------------------------------------------------------
__global__ void zero_kernel() {
    int i = blockIdx.x * 256 + threadIdx.x;
    if (i < 32768)  g_ampool[i] = 0.f;
    if (i < 131072) g_qv1pre[i] = 0.f;
}

// ---------------------------------------------------------------------------
// small branches (q, v1): 64x1024x1024 GEMM partials with K-split.
// grid (8 g, 4 kc, 2 z). Perf-irrelevant (~0.3 GFLOP total).
// ---------------------------------------------------------------------------
__global__ void small_partial(const float* __restrict__ query,
                              const float* __restrict__ value1,
                              const float* __restrict__ Wq,
                              const float* __restrict__ Wv1) {
    const int g = blockIdx.x, kc = blockIdx.y, z = blockIdx.z;
    const float* X = z ? value1 : query;
    const float* W = z ? Wv1 : Wq;
    __shared__ float Xs[16 * 64];
    __shared__ float Ws[16 * 128];
    const int tid = threadIdx.x;
    const int ty = tid >> 4, tx = tid & 15;
    const int n0 = g << 7;
    const int lm = tid >> 2, lk = (tid & 3) << 2;
    const int lk2 = tid >> 4, ln = (tid & 15) << 3;

    float acc[4][8];
#pragma unroll
    for (int i = 0; i < 4; i++)
#pragma unroll
        for (int j = 0; j < 8; j++) acc[i][j] = 0.f;

    const int kbeg = kc * 256, kend = kbeg + 256;
    for (int k0 = kbeg; k0 < kend; k0 += 16) {
        float4 xv = *(const float4*)(X + (size_t)lm * 1024 + k0 + lk);
        float4 w0 = *(const float4*)(W + (size_t)(k0 + lk2) * 1024 + n0 + ln);
        float4 w1 = *(const float4*)(W + (size_t)(k0 + lk2) * 1024 + n0 + ln + 4);
        __syncthreads();
        Xs[(lk + 0) * 64 + lm] = xv.x;
        Xs[(lk + 1) * 64 + lm] = xv.y;
        Xs[(lk + 2) * 64 + lm] = xv.z;
        Xs[(lk + 3) * 64 + lm] = xv.w;
        *(float4*)(Ws + lk2 * 128 + ln) = w0;
        *(float4*)(Ws + lk2 * 128 + ln + 4) = w1;
        __syncthreads();
#pragma unroll
        for (int kk = 0; kk < 16; kk++) {
            float4 a = *(const float4*)(Xs + kk * 64 + (ty << 2));
            float4 b0 = *(const float4*)(Ws + kk * 128 + (tx << 3));
            float4 b1 = *(const float4*)(Ws + kk * 128 + (tx << 3) + 4);
            float av[4] = {a.x, a.y, a.z, a.w};
            float bv[8] = {b0.x, b0.y, b0.z, b0.w, b1.x, b1.y, b1.z, b1.w};
#pragma unroll
            for (int i = 0; i < 4; i++)
#pragma unroll
                for (int j = 0; j < 8; j++) acc[i][j] += av[i] * bv[j];
        }
    }
    float* dst = g_qv1pre + z * 65536;
#pragma unroll
    for (int i = 0; i < 4; i++)
#pragma unroll
        for (int j = 0; j < 8; j++)
            atomicAdd(&dst[((ty << 2) + i) * 1024 + n0 + (tx << 3) + j], acc[i][j]);
}

// bias + celu + GroupNorm for q/v1. grid 128 blocks (0-63 q, 64-127 v1), 256 thr.
__global__ void small_finalize(const float* __restrict__ bq, const float* __restrict__ gq,
                               const float* __restrict__ gbq,
                               const float* __restrict__ bv1, const float* __restrict__ gv1,
                               const float* __restrict__ gbv1) {
    const int row = blockIdx.x;
    const int z = row >> 6, r = row & 63;
    const int tid = threadIdx.x;
    const float* pre = g_qv1pre + z * 65536 + r * 1024;
    const float* bias = z ? bv1 : bq;
    const float* gam  = z ? gv1 : gq;
    const float* bet  = z ? gbv1 : gbq;
    float v[4], s = 0.f, s2 = 0.f;
#pragma unroll
    for (int j = 0; j < 4; j++) {
        int c = tid * 4 + j;
        float x = celu_f(pre[c] + bias[c]);
        v[j] = x; s += x; s2 += x * x;
    }
#pragma unroll
    for (int o = 16; o; o >>= 1) {
        s  += __shfl_xor_sync(0xffffffffu, s, o);
        s2 += __shfl_xor_sync(0xffffffffu, s2, o);
    }
    float mu = s * (1.f / 128.f);
    float var = s2 * (1.f / 128.f) - mu * mu;
    float rs = rsqrtf(var + EPS_F);
    float* o = z ? g_v1gn : g_qgn;
#pragma unroll
    for (int j = 0; j < 4; j++) {
        int c = tid * 4 + j;
        o[r * 1024 + c] = (v[j] - mu) * rs * gam[c] + bet[c];
    }
}

// ---------------------------------------------------------------------------
// Big fused branch kernel. grid 1024 blocks, each owns 64 rows of (B*M).
// Per head g: 64x128 fp32 GEMM (FFMA2) + bias + celu + GroupNorm.
//   IS_K=false: store normalized tile to g_v2.
//   IS_K=true : multiply by q, small GEMM vs Wb, relu, emit logits + am_pool.
// ---------------------------------------------------------------------------
// dynamic smem layout (floats):
//   Xs   [0,1024)   Ws [1024,3072)
//   sS   [3072, 3072+64*132)       (IS_K)   q*k tile, row-major, pad 132
//   WbS  [11520, +8192)            (IS_K)
//   WlS  [19712,+64)  bbS [19776,+64)  qS [19840,+128)  mS [19968,+64) apS [20032,+64)
#define SMEM_K_FLOATS 20096
#define SMEM_V2_FLOATS 3072

template <bool IS_K>
__global__ void __launch_bounds__(256, 2)
big_kernel(const float* __restrict__ X, const float* __restrict__ W,
           const float* __restrict__ bias, const float* __restrict__ gam,
           const float* __restrict__ bet,
           const float* __restrict__ Wb, const float* __restrict__ bb,
           const float* __restrict__ Wl, const float* __restrict__ bl,
           const float* __restrict__ mask) {
    extern __shared__ float sm[];
    float* Xs  = sm;
    float* Ws  = sm + 1024;
    float* sS  = sm + 3072;
    float* WbS = sm + 11520;
    float* WlS = sm + 19712;
    float* bbS = sm + 19776;
    float* qS  = sm + 19840;
    float* mS  = sm + 19968;
    float* apS = sm + 20032;

    const int tid = threadIdx.x;
    const int ty = tid >> 4, tx = tid & 15;
    const int r0 = blockIdx.x << 6;
    const int b = r0 >> 10;
    const int mbase = r0 & 1023;

    if (IS_K) {
        for (int i = tid; i < 8192; i += 256) WbS[i] = Wb[i];
        if (tid < 64) {
            WlS[tid] = Wl[tid];
            bbS[tid] = bb[tid];
            mS[tid] = mask[r0 + tid];
        }
    }

    const float* Xp = X + (size_t)r0 * 1024;
    const int lm = tid >> 2, lk = (tid & 3) << 2;
    const int lk2 = tid >> 4, ln = (tid & 15) << 3;

    for (int g = 0; g < 8; ++g) {
        const int n0 = g << 7;
        if (IS_K) {
            __syncthreads();  // protect qS/apS from previous iteration
            if (tid < 128) qS[tid] = g_qgn[b * 1024 + n0 + tid];
            if (tid < 64) apS[tid] = 0.f;
        }

        uint64_t acc[4][4];
#pragma unroll
        for (int i = 0; i < 4; i++)
#pragma unroll
            for (int p = 0; p < 4; p++) acc[i][p] = 0ull;

        for (int k0 = 0; k0 < 1024; k0 += 16) {
            float4 xv = *(const float4*)(Xp + (size_t)lm * 1024 + k0 + lk);
            float4 w0 = *(const float4*)(W + (size_t)(k0 + lk2) * 1024 + n0 + ln);
            float4 w1 = *(const float4*)(W + (size_t)(k0 + lk2) * 1024 + n0 + ln + 4);
            __syncthreads();
            Xs[(lk + 0) * 64 + lm] = xv.x;
            Xs[(lk + 1) * 64 + lm] = xv.y;
            Xs[(lk + 2) * 64 + lm] = xv.z;
            Xs[(lk + 3) * 64 + lm] = xv.w;
            *(float4*)(Ws + lk2 * 128 + ln) = w0;
            *(float4*)(Ws + lk2 * 128 + ln + 4) = w1;
            __syncthreads();
#pragma unroll
            for (int kk = 0; kk < 16; kk++) {
                float4 a = *(const float4*)(Xs + kk * 64 + (ty << 2));
                const uint64_t* bp = (const uint64_t*)(Ws + kk * 128 + (tx << 3));
                uint64_t b0 = bp[0], b1 = bp[1], b2 = bp[2], b3 = bp[3];
                uint64_t a0 = pack2(a.x, a.x), a1 = pack2(a.y, a.y);
                uint64_t a2 = pack2(a.z, a.z), a3 = pack2(a.w, a.w);
                acc[0][0] = ffma2(a0, b0, acc[0][0]); acc[0][1] = ffma2(a0, b1, acc[0][1]);
                acc[0][2] = ffma2(a0, b2, acc[0][2]); acc[0][3] = ffma2(a0, b3, acc[0][3]);
                acc[1][0] = ffma2(a1, b0, acc[1][0]); acc[1][1] = ffma2(a1, b1, acc[1][1]);
                acc[1][2] = ffma2(a1, b2, acc[1][2]); acc[1][3] = ffma2(a1, b3, acc[1][3]);
                acc[2][0] = ffma2(a2, b0, acc[2][0]); acc[2][1] = ffma2(a2, b1, acc[2][1]);
                acc[2][2] = ffma2(a2, b2, acc[2][2]); acc[2][3] = ffma2(a2, b3, acc[2][3]);
                acc[3][0] = ffma2(a3, b0, acc[3][0]); acc[3][1] = ffma2(a3, b1, acc[3][1]);
                acc[3][2] = ffma2(a3, b2, acc[3][2]); acc[3][3] = ffma2(a3, b3, acc[3][3]);
            }
        }

        // ---- epilogue: bias + celu + GroupNorm (row stats across 16 tx lanes) ----
#pragma unroll
        for (int i = 0; i < 4; i++) {
            float v[8];
#pragma unroll
            for (int p = 0; p < 4; p++) unpack2(acc[i][p], v[2 * p], v[2 * p + 1]);
            float s = 0.f, s2 = 0.f;
#pragma unroll
            for (int j = 0; j < 8; j++) {
                int c = n0 + (tx << 3) + j;
                float x = celu_f(v[j] + __ldg(&bias[c]));
                v[j] = x; s += x; s2 += x * x;
            }
#pragma unroll
            for (int o = 8; o; o >>= 1) {
                s  += __shfl_xor_sync(0xffffffffu, s, o);
                s2 += __shfl_xor_sync(0xffffffffu, s2, o);
            }
            float mu = s * (1.f / 128.f);
            float var = s2 * (1.f / 128.f) - mu * mu;
            float rs = rsqrtf(var + EPS_F);
            if (IS_K) {
#pragma unroll
                for (int j = 0; j < 8; j++) {
                    int c = n0 + (tx << 3) + j;
                    float xn = (v[j] - mu) * rs * __ldg(&gam[c]) + __ldg(&bet[c]);
                    sS[((ty << 2) + i) * 132 + (tx << 3) + j] = xn * qS[(tx << 3) + j];
                }
            } else {
                float o8[8];
#pragma unroll
                for (int j = 0; j < 8; j++) {
                    int c = n0 + (tx << 3) + j;
                    o8[j] = (v[j] - mu) * rs * __ldg(&gam[c]) + __ldg(&bet[c]);
                }
                float4* dst = (float4*)(g_v2 + (size_t)(r0 + (ty << 2) + i) * 1024 +
                                        n0 + (tx << 3));
                dst[0] = make_float4(o8[0], o8[1], o8[2], o8[3]);
                dst[1] = make_float4(o8[4], o8[5], o8[6], o8[7]);
            }
        }

        if (IS_K) {
            __syncthreads();  // sS ready
            // small GEMM: am(64x64) = sS(64x128) @ Wb(128x64); thread tile 4x4
            float am[4][4];
#pragma unroll
            for (int i = 0; i < 4; i++)
#pragma unroll
                for (int j = 0; j < 4; j++) am[i][j] = 0.f;

            for (int k4 = 0; k4 < 128; k4 += 4) {
                float4 av[4];
#pragma unroll
                for (int i = 0; i < 4; i++)
                    av[i] = *(const float4*)(sS + ((ty << 2) + i) * 132 + k4);
                float4 b0 = *(const float4*)(WbS + (k4 + 0) * 64 + (tx << 2));
                float4 b1 = *(const float4*)(WbS + (k4 + 1) * 64 + (tx << 2));
                float4 b2 = *(const float4*)(WbS + (k4 + 2) * 64 + (tx << 2));
                float4 b3 = *(const float4*)(WbS + (k4 + 3) * 64 + (tx << 2));
#pragma unroll
                for (int i = 0; i < 4; i++) {
                    am[i][0] += av[i].x * b0.x; am[i][1] += av[i].x * b0.y;
                    am[i][2] += av[i].x * b0.z; am[i][3] += av[i].x * b0.w;
                    am[i][0] += av[i].y * b1.x; am[i][1] += av[i].y * b1.y;
                    am[i][2] += av[i].y * b1.z; am[i][3] += av[i].y * b1.w;
                    am[i][0] += av[i].z * b2.x; am[i][1] += av[i].z * b2.y;
                    am[i][2] += av[i].z * b2.z; am[i][3] += av[i].z * b2.w;
                    am[i][0] += av[i].w * b3.x; am[i][1] += av[i].w * b3.y;
                    am[i][2] += av[i].w * b3.z; am[i][3] += av[i].w * b3.w;
                }
            }

            // bias + relu, logit partials (dot with Wl over this thread's 4 cols)
            float lp[4];
#pragma unroll
            for (int i = 0; i < 4; i++) {
                float t = 0.f;
#pragma unroll
                for (int j = 0; j < 4; j++) {
                    float a = fmaxf(am[i][j] + bbS[(tx << 2) + j], 0.f);
                    am[i][j] = a;
                    t += a * WlS[(tx << 2) + j];
                }
                lp[i] = t;
            }
#pragma unroll
            for (int o = 8; o; o >>= 1)
#pragma unroll
                for (int i = 0; i < 4; i++) lp[i] += __shfl_xor_sync(0xffffffffu, lp[i], o);
            if (tx == 0) {
                const float blv = __ldg(&bl[0]);
#pragma unroll
                for (int i = 0; i < 4; i++)
                    g_logits[(((b << 3) + g) << 10) + mbase + (ty << 2) + i] = lp[i] + blv;
            }
            // am_pool partials (mask-weighted sum over rows)
#pragma unroll
            for (int j = 0; j < 4; j++) {
                float ap = am[0][j] * mS[(ty << 2) + 0] + am[1][j] * mS[(ty << 2) + 1] +
                           am[2][j] * mS[(ty << 2) + 2] + am[3][j] * mS[(ty << 2) + 3];
                atomicAdd(&apS[(tx << 2) + j], ap);
            }
            __syncthreads();
            if (tid < 64)
                atomicAdd(&g_ampool[(((b << 3) + g) << 6) + tid], apS[tid]);
        }
    }
}

// ---------------------------------------------------------------------------
// finalize: softmax over logits, alpha_channel, pooled_v2, output.
// grid (H=8, B=64), 256 threads.
// ---------------------------------------------------------------------------
__global__ void final_kernel(const float* __restrict__ mask,
                             const float* __restrict__ Wl2,
                             const float* __restrict__ bl2,
                             float* __restrict__ out) {
    const int h = blockIdx.x, b = blockIdx.y;
    const int tid = threadIdx.x;
    const int lane = tid & 31, wrp = tid >> 5;
    __shared__ float wsm[1024];
    __shared__ float redA[8], redB[8], bc[4];
    __shared__ float pm[64], ac[128], psm[256];

    const float* lg = g_logits + (((size_t)b * 8 + h) << 10);
    const float* mrow = mask + ((size_t)b << 10);

    float l[4], mk[4];
    float lmax = -1e30f, msum = 0.f;
#pragma unroll
    for (int k = 0; k < 4; k++) {
        int m = tid + (k << 8);
        mk[k] = mrow[m];
        l[k] = (mk[k] == 0.f) ? -1e9f : lg[m];
        lmax = fmaxf(lmax, l[k]);
        msum += mk[k];
    }
#pragma unroll
    for (int o = 16; o; o >>= 1) {
        lmax = fmaxf(lmax, __shfl_xor_sync(0xffffffffu, lmax, o));
        msum += __shfl_xor_sync(0xffffffffu, msum, o);
    }
    if (lane == 0) { redA[wrp] = lmax; redB[wrp] = msum; }
    __syncthreads();
    if (tid == 0) {
        float a = -1e30f, s = 0.f;
#pragma unroll
        for (int i = 0; i < 8; i++) { a = fmaxf(a, redA[i]); s += redB[i]; }
        bc[0] = a; bc[1] = s;
    }
    __syncthreads();
    const float gmax = bc[0], msumv = bc[1];

    float es = 0.f;
#pragma unroll
    for (int k = 0; k < 4; k++) {
        float e = __expf(l[k] - gmax);
        wsm[tid + (k << 8)] = e;
        es += e;
    }
#pragma unroll
    for (int o = 16; o; o >>= 1) es += __shfl_xor_sync(0xffffffffu, es, o);
    if (lane == 0) redA[wrp] = es;
    __syncthreads();
    if (tid == 0) {
        float s = 0.f;
#pragma unroll
        for (int i = 0; i < 8; i++) s += redA[i];
        bc[2] = s;
    }
    if (tid < 64) pm[tid] = g_ampool[(((b << 3) + h) << 6) + tid] / msumv;
    __syncthreads();
    const float inv = 1.f / bc[2];

    if (tid < 128) {
        float t = bl2[tid];
#pragma unroll 8
        for (int n = 0; n < 64; n++) t += pm[n] * Wl2[n * 128 + tid];
        ac[tid] = 1.f / (1.f + __expf(-t));
    }
    __syncthreads();

    // pooled_v2: 256 threads = 2 m-slices x 128 channels
    const int s2 = tid >> 7, d = tid & 127;
    const float* v2p = g_v2 + ((size_t)(b << 10)) * 1024 + (h << 7) + d;
    float accp = 0.f;
    for (int m = s2; m < 1024; m += 8) {
        accp += wsm[m] * v2p[(size_t)m * 1024];
        accp += wsm[m + 2] * v2p[(size_t)(m + 2) * 1024];
        accp += wsm[m + 4] * v2p[(size_t)(m + 4) * 1024];
        accp += wsm[m + 6] * v2p[(size_t)(m + 6) * 1024];
    }
    psm[tid] = accp;
    __syncthreads();
    if (tid < 128) {
        float p = (psm[tid] + psm[tid + 128]) * inv;
        int oi = (b << 10) + (h << 7) + tid;
        out[oi] = g_v1gn[oi] * p * ac[tid];
    }
}

// ---------------------------------------------------------------------------
// launch
// ---------------------------------------------------------------------------
extern "C" void kernel_launch(void* const* d_in, const int* in_sizes, int n_in,
                              void* d_out, int out_size) {
    const float* query  = (const float*)d_in[0];
    const float* key    = (const float*)d_in[1];
    const float* mask   = (const float*)d_in[2];
    const float* value1 = (const float*)d_in[3];
    const float* value2 = (const float*)d_in[4];
    const float* Wq  = (const float*)d_in[5];
    const float* bq  = (const float*)d_in[6];
    const float* gq  = (const float*)d_in[7];
    const float* gbq = (const float*)d_in[8];
    const float* Wk  = (const float*)d_in[9];
    const float* bk  = (const float*)d_in[10];
    const float* gk  = (const float*)d_in[11];
    const float* gbk = (const float*)d_in[12];
    const float* Wv1  = (const float*)d_in[13];
    const float* bv1  = (const float*)d_in[14];
    const float* gv1  = (const float*)d_in[15];
    const float* gbv1 = (const float*)d_in[16];
    const float* Wv2  = (const float*)d_in[17];
    const float* bv2  = (const float*)d_in[18];
    const float* gv2  = (const float*)d_in[19];
    const float* gbv2 = (const float*)d_in[20];
    const float* Wb  = (const float*)d_in[21];
    const float* bb  = (const float*)d_in[22];
    const float* Wl  = (const float*)d_in[23];
    const float* bl  = (const float*)d_in[24];
    const float* Wl2 = (const float*)d_in[25];
    const float* bl2 = (const float*)d_in[26];
    float* out = (float*)d_out;

    cudaFuncSetAttribute(big_kernel<true>,  cudaFuncAttributeMaxDynamicSharedMemorySize,
                         SMEM_K_FLOATS * 4);
    cudaFuncSetAttribute(big_kernel<false>, cudaFuncAttributeMaxDynamicSharedMemorySize,
                         SMEM_V2_FLOATS * 4);

    zero_kernel<<<512, 256>>>();
    small_partial<<<dim3(8, 4, 2), 256>>>(query, value1, Wq, Wv1);
    small_finalize<<<128, 256>>>(bq, gq, gbq, bv1, gv1, gbv1);
    big_kernel<false><<<1024, 256, SMEM_V2_FLOATS * 4>>>(
        value2, Wv2, bv2, gv2, gbv2, nullptr, nullptr, nullptr, nullptr, nullptr);
    big_kernel<true><<<1024, 256, SMEM_K_FLOATS * 4>>>(
        key, Wk, bk, gk, gbk, Wb, bb, Wl, bl, mask);
    final_kernel<<<dim3(8, 64), 256>>>(mask, Wl2, bl2, out);
}

// round 5
// speedup vs baseline: 1.6546x; 1.6546x over previous
#include <cuda_runtime.h>
#include <cstdint>

// ---------------------------------------------------------------------------
// Problem constants: B=64, M=1024, D=1024, H=8, HD=128, M1=64, ALPHA=1.3, EPS=1e-5
// ---------------------------------------------------------------------------

#define EPS_F 1e-5f

// Scratch (device globals; no allocation allowed)
__device__ float g_v2[67108864];      // (B*M, 1024) v2 after celu+GN  (256 MB)
__device__ float g_qgn[65536];        // (64, 1024)  q after GN
__device__ float g_v1gn[65536];       // (64, 1024)  v1 after GN
__device__ float g_qv1pre[131072];    // (2, 64, 1024) pre-activation partials
__device__ float g_logits[524288];    // (B, H, M)
__device__ float g_ampool[32768];     // (B, H, 64)

// ---------------------------------------------------------------------------
// helpers
// ---------------------------------------------------------------------------
__device__ __forceinline__ float celu_f(float x) {
    return x > 0.f ? x : 1.3f * expm1f(x * (1.0f / 1.3f));
}

__device__ __forceinline__ uint64_t pack2(float lo, float hi) {
    uint64_t r;
    asm("mov.b64 %0, {%1, %2};" : "=l"(r) : "f"(lo), "f"(hi));
    return r;
}
__device__ __forceinline__ void unpack2(uint64_t v, float& lo, float& hi) {
    asm("mov.b64 {%0, %1}, %2;" : "=f"(lo), "=f"(hi) : "l"(v));
}
__device__ __forceinline__ uint64_t ffma2(uint64_t a, uint64_t b, uint64_t c) {
    uint64_t d;
    asm("fma.rn.f32x2 %0, %1, %2, %3;" : "=l"(d) : "l"(a), "l"(b), "l"(c));
    return d;
}

// ---------------------------------------------------------------------------
// zero scratch accumulators (must run every launch; graph is replayed)
// ---------------------------------------------------------------------------
__global__ void zero_kernel() {
    int i = blockIdx.x * 256 + threadIdx.x;
    if (i < 32768)  g_ampool[i] = 0.f;
    if (i < 131072) g_qv1pre[i] = 0.f;
}

// ---------------------------------------------------------------------------
// small branches (q, v1): 64x1024x1024 GEMM partials with K-split.
// grid (8 g, 4 kc, 2 z). Perf-irrelevant (~0.3 GFLOP total).
// ---------------------------------------------------------------------------
__global__ void small_partial(const float* __restrict__ query,
                              const float* __restrict__ value1,
                              const float* __restrict__ Wq,
                              const float* __restrict__ Wv1) {
    const int g = blockIdx.x, kc = blockIdx.y, z = blockIdx.z;
    const float* X = z ? value1 : query;
    const float* W = z ? Wv1 : Wq;
    __shared__ float Xs[16 * 64];
    __shared__ float Ws[16 * 128];
    const int tid = threadIdx.x;
    const int ty = tid >> 4, tx = tid & 15;
    const int n0 = g << 7;
    const int lm = tid >> 2, lk = (tid & 3) << 2;
    const int lk2 = tid >> 4, ln = (tid & 15) << 3;

    float acc[4][8];
#pragma unroll
    for (int i = 0; i < 4; i++)
#pragma unroll
        for (int j = 0; j < 8; j++) acc[i][j] = 0.f;

    const int kbeg = kc * 256, kend = kbeg + 256;
    for (int k0 = kbeg; k0 < kend; k0 += 16) {
        float4 xv = *(const float4*)(X + (size_t)lm * 1024 + k0 + lk);
        float4 w0 = *(const float4*)(W + (size_t)(k0 + lk2) * 1024 + n0 + ln);
        float4 w1 = *(const float4*)(W + (size_t)(k0 + lk2) * 1024 + n0 + ln + 4);
        __syncthreads();
        Xs[(lk + 0) * 64 + lm] = xv.x;
        Xs[(lk + 1) * 64 + lm] = xv.y;
        Xs[(lk + 2) * 64 + lm] = xv.z;
        Xs[(lk + 3) * 64 + lm] = xv.w;
        *(float4*)(Ws + lk2 * 128 + ln) = w0;
        *(float4*)(Ws + lk2 * 128 + ln + 4) = w1;
        __syncthreads();
#pragma unroll
        for (int kk = 0; kk < 16; kk++) {
            float4 a = *(const float4*)(Xs + kk * 64 + (ty << 2));
            float4 b0 = *(const float4*)(Ws + kk * 128 + (tx << 3));
            float4 b1 = *(const float4*)(Ws + kk * 128 + (tx << 3) + 4);
            float av[4] = {a.x, a.y, a.z, a.w};
            float bv[8] = {b0.x, b0.y, b0.z, b0.w, b1.x, b1.y, b1.z, b1.w};
#pragma unroll
            for (int i = 0; i < 4; i++)
#pragma unroll
                for (int j = 0; j < 8; j++) acc[i][j] += av[i] * bv[j];
        }
    }
    float* dst = g_qv1pre + z * 65536;
#pragma unroll
    for (int i = 0; i < 4; i++)
#pragma unroll
        for (int j = 0; j < 8; j++)
            atomicAdd(&dst[((ty << 2) + i) * 1024 + n0 + (tx << 3) + j], acc[i][j]);
}

// bias + celu + GroupNorm for q/v1. grid 128 blocks (0-63 q, 64-127 v1), 256 thr.
__global__ void small_finalize(const float* __restrict__ bq, const float* __restrict__ gq,
                               const float* __restrict__ gbq,
                               const float* __restrict__ bv1, const float* __restrict__ gv1,
                               const float* __restrict__ gbv1) {
    const int row = blockIdx.x;
    const int z = row >> 6, r = row & 63;
    const int tid = threadIdx.x;
    const float* pre = g_qv1pre + z * 65536 + r * 1024;
    const float* bias = z ? bv1 : bq;
    const float* gam  = z ? gv1 : gq;
    const float* bet  = z ? gbv1 : gbq;
    float v[4], s = 0.f, s2 = 0.f;
#pragma unroll
    for (int j = 0; j < 4; j++) {
        int c = tid * 4 + j;
        float x = celu_f(pre[c] + bias[c]);
        v[j] = x; s += x; s2 += x * x;
    }
#pragma unroll
    for (int o = 16; o; o >>= 1) {
        s  += __shfl_xor_sync(0xffffffffu, s, o);
        s2 += __shfl_xor_sync(0xffffffffu, s2, o);
    }
    float mu = s * (1.f / 128.f);
    float var = s2 * (1.f / 128.f) - mu * mu;
    float rs = rsqrtf(var + EPS_F);
    float* o = z ? g_v1gn : g_qgn;
#pragma unroll
    for (int j = 0; j < 4; j++) {
        int c = tid * 4 + j;
        o[r * 1024 + c] = (v[j] - mu) * rs * gam[c] + bet[c];
    }
}

// ---------------------------------------------------------------------------
// Big fused branch kernel. grid 1024 blocks, each owns 64 rows of (B*M).
// Per head g: 64x128 fp32 GEMM (FFMA2, double-buffered smem, reg prefetch)
//   + bias + celu + GroupNorm.
//   IS_K=false: store normalized tile to g_v2.
//   IS_K=true : multiply by q, small GEMM vs Wb, relu, emit logits + am_pool.
//
// dynamic smem layout (floats):
//   Xs   [0, 2048)       2 x [16k][64m]
//   Ws   [2048, 6144)    2 x [16k][128n]
//   sS   [6144, 14592)   (IS_K) q*k tile, 64 rows pitch 132
//   WbS  [14592, 22784)  (IS_K)
//   WlS  [22784,+64) bbS[22848,+64) qS[22912,+128) mS[23040,+64) apS[23104,+64)
// ---------------------------------------------------------------------------
#define SMEM_K_FLOATS  23168
#define SMEM_V2_FLOATS 6144

template <bool IS_K>
__global__ void __launch_bounds__(256, 2)
big_kernel(const float* __restrict__ X, const float* __restrict__ W,
           const float* __restrict__ bias, const float* __restrict__ gam,
           const float* __restrict__ bet,
           const float* __restrict__ Wb, const float* __restrict__ bb,
           const float* __restrict__ Wl, const float* __restrict__ bl,
           const float* __restrict__ mask) {
    extern __shared__ float sm[];
    float* Xs  = sm;            // 2 x 1024
    float* Ws  = sm + 2048;     // 2 x 2048
    float* sS  = sm + 6144;
    float* WbS = sm + 14592;
    float* WlS = sm + 22784;
    float* bbS = sm + 22848;
    float* qS  = sm + 22912;
    float* mS  = sm + 23040;
    float* apS = sm + 23104;

    const int tid = threadIdx.x;
    const int ty = tid >> 4, tx = tid & 15;       // compute tile: rows ty*4+, cols tx*4+ / 64+tx*4+
    const int r0 = blockIdx.x << 6;
    const int b = r0 >> 10;
    const int mbase = r0 & 1023;

    // loader mappings (conflict-free staging)
    const int mxr = tid >> 2, kxr = (tid & 3) << 2;   // X: row mxr, k kxr..+3 (transposed store)
    const int kwr = tid >> 5, nwr = (tid & 31) << 2;  // W: rows kwr & kwr+8, cols nwr..+3

    if (IS_K) {
        for (int i = tid; i < 8192; i += 256) WbS[i] = Wb[i];
        if (tid < 64) {
            WlS[tid] = Wl[tid];
            bbS[tid] = bb[tid];
            mS[tid] = mask[r0 + tid];
        }
    }

    const float* Xp = X + (size_t)r0 * 1024;

    for (int g = 0; g < 8; ++g) {
        const int n0 = g << 7;
        if (IS_K) {
            __syncthreads();  // protect qS/apS from previous iteration readers
            if (tid < 128) qS[tid] = g_qgn[b * 1024 + n0 + tid];
            if (tid < 64) apS[tid] = 0.f;
        }

        uint64_t acc[4][4];
#pragma unroll
        for (int i = 0; i < 4; i++)
#pragma unroll
            for (int p = 0; p < 4; p++) acc[i][p] = 0ull;

        // ---- prologue: stage tile 0 into buffer 0 ----
        {
            float4 xv  = *(const float4*)(Xp + (size_t)mxr * 1024 + kxr);
            float4 wv0 = *(const float4*)(W + (size_t)kwr * 1024 + n0 + nwr);
            float4 wv1 = *(const float4*)(W + (size_t)(kwr + 8) * 1024 + n0 + nwr);
            __syncthreads();   // previous g's compute done before overwriting buffers
            Xs[(kxr + 0) * 64 + mxr] = xv.x;
            Xs[(kxr + 1) * 64 + mxr] = xv.y;
            Xs[(kxr + 2) * 64 + mxr] = xv.z;
            Xs[(kxr + 3) * 64 + mxr] = xv.w;
            *(float4*)(Ws + kwr * 128 + nwr) = wv0;
            *(float4*)(Ws + (kwr + 8) * 128 + nwr) = wv1;
            __syncthreads();
        }

        // ---- mainloop: 64 k-tiles, double-buffered ----
        for (int t = 0; t < 64; t++) {
            float4 xv, wv0, wv1;
            if (t < 63) {
                const int k0 = (t + 1) << 4;
                xv  = *(const float4*)(Xp + (size_t)mxr * 1024 + k0 + kxr);
                wv0 = *(const float4*)(W + (size_t)(k0 + kwr) * 1024 + n0 + nwr);
                wv1 = *(const float4*)(W + (size_t)(k0 + kwr + 8) * 1024 + n0 + nwr);
            }
            const float* Xc = Xs + (t & 1) * 1024;
            const float* Wc = Ws + (t & 1) * 2048;
#pragma unroll
            for (int kk = 0; kk < 16; kk++) {
                float4 a = *(const float4*)(Xc + kk * 64 + (ty << 2));
                ulonglong2 blo = *(const ulonglong2*)(Wc + kk * 128 + (tx << 2));
                ulonglong2 bhi = *(const ulonglong2*)(Wc + kk * 128 + 64 + (tx << 2));
                uint64_t a0 = pack2(a.x, a.x), a1 = pack2(a.y, a.y);
                uint64_t a2 = pack2(a.z, a.z), a3 = pack2(a.w, a.w);
                acc[0][0] = ffma2(a0, blo.x, acc[0][0]);
                acc[0][1] = ffma2(a0, blo.y, acc[0][1]);
                acc[0][2] = ffma2(a0, bhi.x, acc[0][2]);
                acc[0][3] = ffma2(a0, bhi.y, acc[0][3]);
                acc[1][0] = ffma2(a1, blo.x, acc[1][0]);
                acc[1][1] = ffma2(a1, blo.y, acc[1][1]);
                acc[1][2] = ffma2(a1, bhi.x, acc[1][2]);
                acc[1][3] = ffma2(a1, bhi.y, acc[1][3]);
                acc[2][0] = ffma2(a2, blo.x, acc[2][0]);
                acc[2][1] = ffma2(a2, blo.y, acc[2][1]);
                acc[2][2] = ffma2(a2, bhi.x, acc[2][2]);
                acc[2][3] = ffma2(a2, bhi.y, acc[2][3]);
                acc[3][0] = ffma2(a3, blo.x, acc[3][0]);
                acc[3][1] = ffma2(a3, blo.y, acc[3][1]);
                acc[3][2] = ffma2(a3, bhi.x, acc[3][2]);
                acc[3][3] = ffma2(a3, bhi.y, acc[3][3]);
            }
            __syncthreads();  // everyone done reading buf[t&1]
            if (t < 63) {
                float* Xn = Xs + ((t + 1) & 1) * 1024;
                float* Wn = Ws + ((t + 1) & 1) * 2048;
                Xn[(kxr + 0) * 64 + mxr] = xv.x;
                Xn[(kxr + 1) * 64 + mxr] = xv.y;
                Xn[(kxr + 2) * 64 + mxr] = xv.z;
                Xn[(kxr + 3) * 64 + mxr] = xv.w;
                *(float4*)(Wn + kwr * 128 + nwr) = wv0;
                *(float4*)(Wn + (kwr + 8) * 128 + nwr) = wv1;
                __syncthreads();
            }
        }

        // ---- epilogue: bias + celu + GroupNorm (row stats across 16 tx lanes) ----
#pragma unroll
        for (int i = 0; i < 4; i++) {
            float v[8];
            unpack2(acc[i][0], v[0], v[1]);
            unpack2(acc[i][1], v[2], v[3]);
            unpack2(acc[i][2], v[4], v[5]);
            unpack2(acc[i][3], v[6], v[7]);
            float s = 0.f, s2 = 0.f;
#pragma unroll
            for (int j = 0; j < 8; j++) {
                const int cl = (j < 4) ? ((tx << 2) + j) : (64 + (tx << 2) + (j - 4));
                float x = celu_f(v[j] + __ldg(&bias[n0 + cl]));
                v[j] = x; s += x; s2 += x * x;
            }
#pragma unroll
            for (int o = 8; o; o >>= 1) {
                s  += __shfl_xor_sync(0xffffffffu, s, o);
                s2 += __shfl_xor_sync(0xffffffffu, s2, o);
            }
            float mu = s * (1.f / 128.f);
            float var = s2 * (1.f / 128.f) - mu * mu;
            float rs = rsqrtf(var + EPS_F);
            if (IS_K) {
#pragma unroll
                for (int j = 0; j < 8; j++) {
                    const int cl = (j < 4) ? ((tx << 2) + j) : (64 + (tx << 2) + (j - 4));
                    float xn = (v[j] - mu) * rs * __ldg(&gam[n0 + cl]) + __ldg(&bet[n0 + cl]);
                    sS[((ty << 2) + i) * 132 + cl] = xn * qS[cl];
                }
            } else {
                float o8[8];
#pragma unroll
                for (int j = 0; j < 8; j++) {
                    const int cl = (j < 4) ? ((tx << 2) + j) : (64 + (tx << 2) + (j - 4));
                    o8[j] = (v[j] - mu) * rs * __ldg(&gam[n0 + cl]) + __ldg(&bet[n0 + cl]);
                }
                float* dstp = g_v2 + (size_t)(r0 + (ty << 2) + i) * 1024 + n0;
                *(float4*)(dstp + (tx << 2))      = make_float4(o8[0], o8[1], o8[2], o8[3]);
                *(float4*)(dstp + 64 + (tx << 2)) = make_float4(o8[4], o8[5], o8[6], o8[7]);
            }
        }

        if (IS_K) {
            __syncthreads();  // sS ready
            // small GEMM: am(64x64) = sS(64x128) @ Wb(128x64); thread tile 4x4
            float am[4][4];
#pragma unroll
            for (int i = 0; i < 4; i++)
#pragma unroll
                for (int j = 0; j < 4; j++) am[i][j] = 0.f;

            for (int k4 = 0; k4 < 128; k4 += 4) {
                float4 av[4];
#pragma unroll
                for (int i = 0; i < 4; i++)
                    av[i] = *(const float4*)(sS + ((ty << 2) + i) * 132 + k4);
                float4 b0 = *(const float4*)(WbS + (k4 + 0) * 64 + (tx << 2));
                float4 b1 = *(const float4*)(WbS + (k4 + 1) * 64 + (tx << 2));
                float4 b2 = *(const float4*)(WbS + (k4 + 2) * 64 + (tx << 2));
                float4 b3 = *(const float4*)(WbS + (k4 + 3) * 64 + (tx << 2));
#pragma unroll
                for (int i = 0; i < 4; i++) {
                    am[i][0] += av[i].x * b0.x; am[i][1] += av[i].x * b0.y;
                    am[i][2] += av[i].x * b0.z; am[i][3] += av[i].x * b0.w;
                    am[i][0] += av[i].y * b1.x; am[i][1] += av[i].y * b1.y;
                    am[i][2] += av[i].y * b1.z; am[i][3] += av[i].y * b1.w;
                    am[i][0] += av[i].z * b2.x; am[i][1] += av[i].z * b2.y;
                    am[i][2] += av[i].z * b2.z; am[i][3] += av[i].z * b2.w;
                    am[i][0] += av[i].w * b3.x; am[i][1] += av[i].w * b3.y;
                    am[i][2] += av[i].w * b3.z; am[i][3] += av[i].w * b3.w;
                }
            }

            // bias + relu, logit partials (dot with Wl over this thread's 4 cols)
            float lp[4];
#pragma unroll
            for (int i = 0; i < 4; i++) {
                float t = 0.f;
#pragma unroll
                for (int j = 0; j < 4; j++) {
                    float a = fmaxf(am[i][j] + bbS[(tx << 2) + j], 0.f);
                    am[i][j] = a;
                    t += a * WlS[(tx << 2) + j];
                }
                lp[i] = t;
            }
#pragma unroll
            for (int o = 8; o; o >>= 1)
#pragma unroll
                for (int i = 0; i < 4; i++) lp[i] += __shfl_xor_sync(0xffffffffu, lp[i], o);
            if (tx == 0) {
                const float blv = __ldg(&bl[0]);
#pragma unroll
                for (int i = 0; i < 4; i++)
                    g_logits[(((b << 3) + g) << 10) + mbase + (ty << 2) + i] = lp[i] + blv;
            }
            // am_pool partials (mask-weighted sum over rows)
#pragma unroll
            for (int j = 0; j < 4; j++) {
                float ap = am[0][j] * mS[(ty << 2) + 0] + am[1][j] * mS[(ty << 2) + 1] +
                           am[2][j] * mS[(ty << 2) + 2] + am[3][j] * mS[(ty << 2) + 3];
                atomicAdd(&apS[(tx << 2) + j], ap);
            }
            __syncthreads();
            if (tid < 64)
                atomicAdd(&g_ampool[(((b << 3) + g) << 6) + tid], apS[tid]);
        }
    }
}

// ---------------------------------------------------------------------------
// finalize: softmax over logits, alpha_channel, pooled_v2, output.
// grid (H=8, B=64), 256 threads.
// ---------------------------------------------------------------------------
__global__ void final_kernel(const float* __restrict__ mask,
                             const float* __restrict__ Wl2,
                             const float* __restrict__ bl2,
                             float* __restrict__ out) {
    const int h = blockIdx.x, b = blockIdx.y;
    const int tid = threadIdx.x;
    const int lane = tid & 31, wrp = tid >> 5;
    __shared__ float wsm[1024];
    __shared__ float redA[8], redB[8], bc[4];
    __shared__ float pm[64], ac[128], psm[256];

    const float* lg = g_logits + (((size_t)b * 8 + h) << 10);
    const float* mrow = mask + ((size_t)b << 10);

    float l[4], mk[4];
    float lmax = -1e30f, msum = 0.f;
#pragma unroll
    for (int k = 0; k < 4; k++) {
        int m = tid + (k << 8);
        mk[k] = mrow[m];
        l[k] = (mk[k] == 0.f) ? -1e9f : lg[m];
        lmax = fmaxf(lmax, l[k]);
        msum += mk[k];
    }
#pragma unroll
    for (int o = 16; o; o >>= 1) {
        lmax = fmaxf(lmax, __shfl_xor_sync(0xffffffffu, lmax, o));
        msum += __shfl_xor_sync(0xffffffffu, msum, o);
    }
    if (lane == 0) { redA[wrp] = lmax; redB[wrp] = msum; }
    __syncthreads();
    if (tid == 0) {
        float a = -1e30f, s = 0.f;
#pragma unroll
        for (int i = 0; i < 8; i++) { a = fmaxf(a, redA[i]); s += redB[i]; }
        bc[0] = a; bc[1] = s;
    }
    __syncthreads();
    const float gmax = bc[0], msumv = bc[1];

    float es = 0.f;
#pragma unroll
    for (int k = 0; k < 4; k++) {
        float e = __expf(l[k] - gmax);
        wsm[tid + (k << 8)] = e;
        es += e;
    }
#pragma unroll
    for (int o = 16; o; o >>= 1) es += __shfl_xor_sync(0xffffffffu, es, o);
    if (lane == 0) redA[wrp] = es;
    __syncthreads();
    if (tid == 0) {
        float s = 0.f;
#pragma unroll
        for (int i = 0; i < 8; i++) s += redA[i];
        bc[2] = s;
    }
    if (tid < 64) pm[tid] = g_ampool[(((b << 3) + h) << 6) + tid] / msumv;
    __syncthreads();
    const float inv = 1.f / bc[2];

    if (tid < 128) {
        float t = bl2[tid];
#pragma unroll 8
        for (int n = 0; n < 64; n++) t += pm[n] * Wl2[n * 128 + tid];
        ac[tid] = 1.f / (1.f + __expf(-t));
    }
    __syncthreads();

    // pooled_v2: 256 threads = 2 m-slices x 128 channels
    const int s2 = tid >> 7, d = tid & 127;
    const float* v2p = g_v2 + ((size_t)(b << 10)) * 1024 + (h << 7) + d;
    float accp = 0.f;
    for (int m = s2; m < 1024; m += 8) {
        accp += wsm[m] * v2p[(size_t)m * 1024];
        accp += wsm[m + 2] * v2p[(size_t)(m + 2) * 1024];
        accp += wsm[m + 4] * v2p[(size_t)(m + 4) * 1024];
        accp += wsm[m + 6] * v2p[(size_t)(m + 6) * 1024];
    }
    psm[tid] = accp;
    __syncthreads();
    if (tid < 128) {
        float p = (psm[tid] + psm[tid + 128]) * inv;
        int oi = (b << 10) + (h << 7) + tid;
        out[oi] = g_v1gn[oi] * p * ac[tid];
    }
}

// ---------------------------------------------------------------------------
// launch
// ---------------------------------------------------------------------------
extern "C" void kernel_launch(void* const* d_in, const int* in_sizes, int n_in,
                              void* d_out, int out_size) {
    const float* query  = (const float*)d_in[0];
    const float* key    = (const float*)d_in[1];
    const float* mask   = (const float*)d_in[2];
    const float* value1 = (const float*)d_in[3];
    const float* value2 = (const float*)d_in[4];
    const float* Wq  = (const float*)d_in[5];
    const float* bq  = (const float*)d_in[6];
    const float* gq  = (const float*)d_in[7];
    const float* gbq = (const float*)d_in[8];
    const float* Wk  = (const float*)d_in[9];
    const float* bk  = (const float*)d_in[10];
    const float* gk  = (const float*)d_in[11];
    const float* gbk = (const float*)d_in[12];
    const float* Wv1  = (const float*)d_in[13];
    const float* bv1  = (const float*)d_in[14];
    const float* gv1  = (const float*)d_in[15];
    const float* gbv1 = (const float*)d_in[16];
    const float* Wv2  = (const float*)d_in[17];
    const float* bv2  = (const float*)d_in[18];
    const float* gv2  = (const float*)d_in[19];
    const float* gbv2 = (const float*)d_in[20];
    const float* Wb  = (const float*)d_in[21];
    const float* bb  = (const float*)d_in[22];
    const float* Wl  = (const float*)d_in[23];
    const float* bl  = (const float*)d_in[24];
    const float* Wl2 = (const float*)d_in[25];
    const float* bl2 = (const float*)d_in[26];
    float* out = (float*)d_out;

    cudaFuncSetAttribute(big_kernel<true>,  cudaFuncAttributeMaxDynamicSharedMemorySize,
                         SMEM_K_FLOATS * 4);
    cudaFuncSetAttribute(big_kernel<false>, cudaFuncAttributeMaxDynamicSharedMemorySize,
                         SMEM_V2_FLOATS * 4);

    zero_kernel<<<512, 256>>>();
    small_partial<<<dim3(8, 4, 2), 256>>>(query, value1, Wq, Wv1);
    small_finalize<<<128, 256>>>(bq, gq, gbq, bv1, gv1, gbv1);
    big_kernel<false><<<1024, 256, SMEM_V2_FLOATS * 4>>>(
        value2, Wv2, bv2, gv2, gbv2, nullptr, nullptr, nullptr, nullptr, nullptr);
    big_kernel<true><<<1024, 256, SMEM_K_FLOATS * 4>>>(
        key, Wk, bk, gk, gbk, Wb, bb, Wl, bl, mask);
    final_kernel<<<dim3(8, 64), 256>>>(mask, Wl2, bl2, out);
}

// round 8
// speedup vs baseline: 2.7062x; 1.6356x over previous
#include <cuda_runtime.h>
#include <cuda_bf16.h>
#include <cstdint>

#define EPS_F 1e-5f

__device__ float g_v2[67108864];      // (B*M, 1024) v2 after celu+GN
__device__ float g_kq[67108864];      // (B*M, 1024) GN(celu(k)) * q
__device__ float g_qgn[65536];
__device__ float g_v1gn[65536];
__device__ float g_qv1pre[131072];
__device__ float g_logits[524288];    // (B, H, M)
__device__ float g_ampool[32768];     // (B, H, 64)

// ---------------- helpers ----------------
__device__ __forceinline__ uint32_t smem_to_u32(const void* p) {
    uint32_t a;
    asm("{ .reg .u64 t; cvta.to.shared.u64 t, %1; cvt.u32.u64 %0, t; }" : "=r"(a) : "l"(p));
    return a;
}
__device__ __forceinline__ float celu_f(float x) {
    return x > 0.f ? x : 1.3f * expm1f(x * (1.0f / 1.3f));
}
__device__ __forceinline__ void cvt_split2(float a, float b, uint32_t& hi, uint32_t& lo) {
    __nv_bfloat16 ha = __float2bfloat16(a);
    __nv_bfloat16 hb = __float2bfloat16(b);
    __nv_bfloat16 la = __float2bfloat16(a - __bfloat162float(ha));
    __nv_bfloat16 lb = __float2bfloat16(b - __bfloat162float(hb));
    __nv_bfloat162 h2(ha, hb), l2(la, lb);
    hi = *reinterpret_cast<uint32_t*>(&h2);
    lo = *reinterpret_cast<uint32_t*>(&l2);
}
__device__ __forceinline__ void ldsm4(uint32_t* r, uint32_t addr) {
    asm volatile("ldmatrix.sync.aligned.m8n8.x4.shared.b16 {%0,%1,%2,%3}, [%4];"
                 : "=r"(r[0]), "=r"(r[1]), "=r"(r[2]), "=r"(r[3]) : "r"(addr));
}
__device__ __forceinline__ void mma16816(float* d, const uint32_t* a,
                                         const uint32_t b0, const uint32_t b1) {
    asm volatile(
        "mma.sync.aligned.m16n8k16.row.col.f32.bf16.bf16.f32 "
        "{%0,%1,%2,%3}, {%4,%5,%6,%7}, {%8,%9}, {%0,%1,%2,%3};"
        : "+f"(d[0]), "+f"(d[1]), "+f"(d[2]), "+f"(d[3])
        : "r"(a[0]), "r"(a[1]), "r"(a[2]), "r"(a[3]), "r"(b0), "r"(b1));
}

// ---------------- zero scratch ----------------
__global__ void zero_kernel() {
    int i = blockIdx.x * 256 + threadIdx.x;
    if (i < 32768)  g_ampool[i] = 0.f;
    if (i < 131072) g_qv1pre[i] = 0.f;
}

// ---------------- small branches (q, v1) ----------------
__global__ void small_partial(const float* __restrict__ query,
                              const float* __restrict__ value1,
                              const float* __restrict__ Wq,
                              const float* __restrict__ Wv1) {
    const int g = blockIdx.x, kc = blockIdx.y, z = blockIdx.z;
    const float* X = z ? value1 : query;
    const float* W = z ? Wv1 : Wq;
    __shared__ float Xs[16 * 64];
    __shared__ float Ws[16 * 128];
    const int tid = threadIdx.x;
    const int ty = tid >> 4, tx = tid & 15;
    const int n0 = g << 7;
    const int lm = tid >> 2, lk = (tid & 3) << 2;
    const int lk2 = tid >> 4, ln = (tid & 15) << 3;

    float acc[4][8];
#pragma unroll
    for (int i = 0; i < 4; i++)
#pragma unroll
        for (int j = 0; j < 8; j++) acc[i][j] = 0.f;

    const int kbeg = kc * 256, kend = kbeg + 256;
    for (int k0 = kbeg; k0 < kend; k0 += 16) {
        float4 xv = *(const float4*)(X + (size_t)lm * 1024 + k0 + lk);
        float4 w0 = *(const float4*)(W + (size_t)(k0 + lk2) * 1024 + n0 + ln);
        float4 w1 = *(const float4*)(W + (size_t)(k0 + lk2) * 1024 + n0 + ln + 4);
        __syncthreads();
        Xs[(lk + 0) * 64 + lm] = xv.x;
        Xs[(lk + 1) * 64 + lm] = xv.y;
        Xs[(lk + 2) * 64 + lm] = xv.z;
        Xs[(lk + 3) * 64 + lm] = xv.w;
        *(float4*)(Ws + lk2 * 128 + ln) = w0;
        *(float4*)(Ws + lk2 * 128 + ln + 4) = w1;
        __syncthreads();
#pragma unroll
        for (int kk = 0; kk < 16; kk++) {
            float4 a = *(const float4*)(Xs + kk * 64 + (ty << 2));
            float4 b0 = *(const float4*)(Ws + kk * 128 + (tx << 3));
            float4 b1 = *(const float4*)(Ws + kk * 128 + (tx << 3) + 4);
            float av[4] = {a.x, a.y, a.z, a.w};
            float bv[8] = {b0.x, b0.y, b0.z, b0.w, b1.x, b1.y, b1.z, b1.w};
#pragma unroll
            for (int i = 0; i < 4; i++)
#pragma unroll
                for (int j = 0; j < 8; j++) acc[i][j] += av[i] * bv[j];
        }
    }
    float* dst = g_qv1pre + z * 65536;
#pragma unroll
    for (int i = 0; i < 4; i++)
#pragma unroll
        for (int j = 0; j < 8; j++)
            atomicAdd(&dst[((ty << 2) + i) * 1024 + n0 + (tx << 3) + j], acc[i][j]);
}

__global__ void small_finalize(const float* __restrict__ bq, const float* __restrict__ gq,
                               const float* __restrict__ gbq,
                               const float* __restrict__ bv1, const float* __restrict__ gv1,
                               const float* __restrict__ gbv1) {
    const int row = blockIdx.x;
    const int z = row >> 6, r = row & 63;
    const int tid = threadIdx.x;
    const float* pre = g_qv1pre + z * 65536 + r * 1024;
    const float* bias = z ? bv1 : bq;
    const float* gam  = z ? gv1 : gq;
    const float* bet  = z ? gbv1 : gbq;
    float v[4], s = 0.f, s2 = 0.f;
#pragma unroll
    for (int j = 0; j < 4; j++) {
        int c = tid * 4 + j;
        float x = celu_f(pre[c] + bias[c]);
        v[j] = x; s += x; s2 += x * x;
    }
#pragma unroll
    for (int o = 16; o; o >>= 1) {
        s  += __shfl_xor_sync(0xffffffffu, s, o);
        s2 += __shfl_xor_sync(0xffffffffu, s2, o);
    }
    float mu = s * (1.f / 128.f);
    float var = s2 * (1.f / 128.f) - mu * mu;
    float rs = rsqrtf(var + EPS_F);
    float* o = z ? g_v1gn : g_qgn;
#pragma unroll
    for (int j = 0; j < 4; j++) {
        int c = tid * 4 + j;
        o[r * 1024 + c] = (v[j] - mu) * rs * gam[c] + bet[c];
    }
}

// ---------------------------------------------------------------------------
// mma.sync bf16-split GEMM + fused celu/GN epilogue.
// D[128x128] = X[128 x 1024] @ W[1024 x 128], fp32-equiv via hihi+hilo+lohi.
// QMUL=false -> g_v2 ; QMUL=true -> g_kq (multiplied by g_qgn).
// grid 4096 (512 m-tiles x 8 n-tiles), 256 thr (8 warps, 2m x 4n).
// n-tile 128 = exactly one GN head -> per-row GN inside the CTA.
//
// smem (bytes):
//   A   [0, 40960)      : [buf2][hi/lo][128 rows][pitch 40 bf16]
//   B   [40960, 81920)  : [buf2][hi/lo][128 nrow][pitch 40 bf16]  ([n][k] layout)
//   C   [81920, 149504) : 128 x 132 fp32
//   qS  [149504, 150016)
// ---------------------------------------------------------------------------
#define SMA 0
#define SMB 40960
#define SMC 81920
#define SMQ 149504
#define SM_GEMM_TOTAL 150016

template <bool QMUL>
__global__ void __launch_bounds__(256, 1)
gemm_kernel(const float* __restrict__ X, const float* __restrict__ W,
            const float* __restrict__ bias, const float* __restrict__ gam,
            const float* __restrict__ bet) {
    extern __shared__ char smem[];
    const uint32_t su = smem_to_u32(smem);
    const int tid = threadIdx.x, lane = tid & 31, wid = tid >> 5;
    const int mwarp = wid >> 2, nwarp = wid & 3;
    const int r0 = (int)(blockIdx.x >> 3) * 128;
    const int n0 = (int)(blockIdx.x & 7) * 128;
    const int b = r0 >> 10;

    float* qS = (float*)(smem + SMQ);
    if (QMUL && tid < 128) qS[tid] = g_qgn[b * 1024 + n0 + tid];

    // ldmatrix per-lane offset: tiles in order (m0k0),(m8k0),(m0k8),(m8k8)
    const int rowL = (lane & 7) + ((lane >> 3) & 1) * 8;
    const int kL8 = (lane >> 4) * 8;
    const uint32_t lmoff = (uint32_t)(rowL * 80 + kL8 * 2);

    // staging mappings
    const int arow = tid >> 1, akh = (tid & 1) << 4;      // A: row, k-half(16)
    const int bnn = tid & 127, bkh = (tid >> 7) << 4;     // B: n, k-half(16)

    float d[4][4][4];
#pragma unroll
    for (int i = 0; i < 4; i++)
#pragma unroll
        for (int j = 0; j < 4; j++)
#pragma unroll
            for (int u = 0; u < 4; u++) d[i][j][u] = 0.f;

    const float* Ap = X + (size_t)(r0 + arow) * 1024 + akh;
    const float* Bp = W + (size_t)bkh * 1024 + n0 + bnn;

    // ---- prologue: stage chunk 0 into buf 0 ----
    {
        float4 xr[4];
        float wr[16];
#pragma unroll
        for (int j = 0; j < 4; j++) xr[j] = *(const float4*)(Ap + j * 4);
#pragma unroll
        for (int kk = 0; kk < 16; kk++) wr[kk] = Bp[(size_t)kk * 1024];
        char* ah = smem + SMA;
        char* al = ah + 10240;
#pragma unroll
        for (int j = 0; j < 4; j++) {
            uint32_t h0, l0, h1, l1;
            cvt_split2(xr[j].x, xr[j].y, h0, l0);
            cvt_split2(xr[j].z, xr[j].w, h1, l1);
            uint32_t off = (uint32_t)(arow * 80 + (akh + j * 4) * 2);
            *(uint2*)(ah + off) = make_uint2(h0, h1);
            *(uint2*)(al + off) = make_uint2(l0, l1);
        }
        char* bh = smem + SMB;
        char* bl = bh + 10240;
#pragma unroll
        for (int kk = 0; kk < 16; kk += 4) {
            uint32_t h0, l0, h1, l1;
            cvt_split2(wr[kk], wr[kk + 1], h0, l0);
            cvt_split2(wr[kk + 2], wr[kk + 3], h1, l1);
            uint32_t off = (uint32_t)(bnn * 80 + (bkh + kk) * 2);
            *(uint2*)(bh + off) = make_uint2(h0, h1);
            *(uint2*)(bl + off) = make_uint2(l0, l1);
        }
        __syncthreads();
    }

    // ---- mainloop: 32 k-chunks of 32, double-buffered ----
    for (int t = 0; t < 32; t++) {
        float4 xr[4];
        float wr[16];
        if (t < 31) {
            const int k0 = (t + 1) << 5;
#pragma unroll
            for (int j = 0; j < 4; j++) xr[j] = *(const float4*)(Ap + k0 + j * 4);
#pragma unroll
            for (int kk = 0; kk < 16; kk++) wr[kk] = Bp[(size_t)(k0 + kk) * 1024];
        }
        // compute on buf t&1
        {
            const uint32_t abase = su + SMA + (t & 1) * 20480 +
                                   (uint32_t)(mwarp * 64 * 80) + lmoff;
            const uint32_t bbase = su + SMB + (t & 1) * 20480 +
                                   (uint32_t)(nwarp * 32 * 80) + lmoff;
#pragma unroll
            for (int sl = 0; sl < 2; sl++) {
                uint32_t Ah[4][4], Al[4][4], Bh[4][2], Bl[4][2];
#pragma unroll
                for (int fm = 0; fm < 4; fm++) {
                    ldsm4(Ah[fm], abase + fm * (16 * 80) + sl * 32);
                    ldsm4(Al[fm], abase + 10240 + fm * (16 * 80) + sl * 32);
                }
#pragma unroll
                for (int g = 0; g < 2; g++) {
                    uint32_t tm[4];
                    ldsm4(tm, bbase + g * (16 * 80) + sl * 32);
                    Bh[2 * g][0] = tm[0]; Bh[2 * g][1] = tm[2];
                    Bh[2 * g + 1][0] = tm[1]; Bh[2 * g + 1][1] = tm[3];
                    ldsm4(tm, bbase + 10240 + g * (16 * 80) + sl * 32);
                    Bl[2 * g][0] = tm[0]; Bl[2 * g][1] = tm[2];
                    Bl[2 * g + 1][0] = tm[1]; Bl[2 * g + 1][1] = tm[3];
                }
#pragma unroll
                for (int fm = 0; fm < 4; fm++)
#pragma unroll
                    for (int fn = 0; fn < 4; fn++) {
                        mma16816(d[fm][fn], Ah[fm], Bh[fn][0], Bh[fn][1]);
                        mma16816(d[fm][fn], Ah[fm], Bl[fn][0], Bl[fn][1]);
                        mma16816(d[fm][fn], Al[fm], Bh[fn][0], Bh[fn][1]);
                    }
            }
        }
        __syncthreads();
        if (t < 31) {
            const int buf = (t + 1) & 1;
            char* ah = smem + SMA + buf * 20480;
            char* al = ah + 10240;
#pragma unroll
            for (int j = 0; j < 4; j++) {
                uint32_t h0, l0, h1, l1;
                cvt_split2(xr[j].x, xr[j].y, h0, l0);
                cvt_split2(xr[j].z, xr[j].w, h1, l1);
                uint32_t off = (uint32_t)(arow * 80 + (akh + j * 4) * 2);
                *(uint2*)(ah + off) = make_uint2(h0, h1);
                *(uint2*)(al + off) = make_uint2(l0, l1);
            }
            char* bh = smem + SMB + buf * 20480;
            char* bl = bh + 10240;
#pragma unroll
            for (int kk = 0; kk < 16; kk += 4) {
                uint32_t h0, l0, h1, l1;
                cvt_split2(wr[kk], wr[kk + 1], h0, l0);
                cvt_split2(wr[kk + 2], wr[kk + 3], h1, l1);
                uint32_t off = (uint32_t)(bnn * 80 + (bkh + kk) * 2);
                *(uint2*)(bh + off) = make_uint2(h0, h1);
                *(uint2*)(bl + off) = make_uint2(l0, l1);
            }
            __syncthreads();
        }
    }

    // ---- epilogue: frags -> smem, then per-row bias+celu+GN ----
    float* Cs = (float*)(smem + SMC);
    {
        const int mb = mwarp * 64, nb = nwarp * 32;
        const int r = lane >> 2, c = (lane & 3) * 2;
#pragma unroll
        for (int fm = 0; fm < 4; fm++)
#pragma unroll
            for (int fn = 0; fn < 4; fn++) {
                const int rr = mb + fm * 16 + r;
                const int cc = nb + fn * 8 + c;
                *(float2*)&Cs[rr * 132 + cc] = make_float2(d[fm][fn][0], d[fm][fn][1]);
                *(float2*)&Cs[(rr + 8) * 132 + cc] = make_float2(d[fm][fn][2], d[fm][fn][3]);
            }
    }
    __syncthreads();
    {
        const int row = tid >> 1, half = tid & 1;
        const int c0 = half * 64;
        float v[64];
        float s = 0.f, s2 = 0.f;
#pragma unroll
        for (int j = 0; j < 16; j++) {
            float4 x4 = *(const float4*)&Cs[row * 132 + c0 + j * 4];
            float* px = (float*)&x4;
#pragma unroll
            for (int u = 0; u < 4; u++) {
                float x = celu_f(px[u] + __ldg(&bias[n0 + c0 + j * 4 + u]));
                v[j * 4 + u] = x; s += x; s2 += x * x;
            }
        }
        s  += __shfl_xor_sync(0xffffffffu, s, 1);
        s2 += __shfl_xor_sync(0xffffffffu, s2, 1);
        const float mu = s * (1.f / 128.f);
        const float rs = rsqrtf(s2 * (1.f / 128.f) - mu * mu + EPS_F);
        float* outp = (QMUL ? g_kq : g_v2) + (size_t)(r0 + row) * 1024 + n0 + c0;
#pragma unroll
        for (int j = 0; j < 16; j++) {
            float4 o;
            float* po = (float*)&o;
#pragma unroll
            for (int u = 0; u < 4; u++) {
                const int ch = n0 + c0 + j * 4 + u;
                float xn = (v[j * 4 + u] - mu) * rs * __ldg(&gam[ch]) + __ldg(&bet[ch]);
                if (QMUL) xn *= qS[c0 + j * 4 + u];
                po[u] = xn;
            }
            *(float4*)(outp + j * 4) = o;
        }
    }
}

// ---------------------------------------------------------------------------
// attn: am = relu(g_kq @ Wb + bb); logits = am@Wl+bl; ampool partials.
// ---------------------------------------------------------------------------
__global__ void __launch_bounds__(256, 2)
attn_kernel(const float* __restrict__ Wb, const float* __restrict__ bb,
            const float* __restrict__ Wl, const float* __restrict__ bl,
            const float* __restrict__ mask) {
    __shared__ float WbS[8192];
    __shared__ float WlS[64], bbS[64], mS[64], apS[64];
    const int tid = threadIdx.x;
    const int ty = tid >> 4, tx = tid & 15;
    const int r0 = blockIdx.x << 6;
    const int b = r0 >> 10, mbase = r0 & 1023;

    for (int i = tid; i < 8192; i += 256) WbS[i] = Wb[i];
    if (tid < 64) {
        WlS[tid] = Wl[tid];
        bbS[tid] = bb[tid];
        mS[tid] = mask[r0 + tid];
    }
    __syncthreads();

    for (int g = 0; g < 8; ++g) {
        if (tid < 64) apS[tid] = 0.f;
        __syncthreads();

        float am[4][4];
#pragma unroll
        for (int i = 0; i < 4; i++)
#pragma unroll
            for (int j = 0; j < 4; j++) am[i][j] = 0.f;

        const float* sp = g_kq + (size_t)r0 * 1024 + (g << 7);
        for (int k4 = 0; k4 < 128; k4 += 4) {
            float4 av[4];
#pragma unroll
            for (int i = 0; i < 4; i++)
                av[i] = *(const float4*)(sp + (size_t)((ty << 2) + i) * 1024 + k4);
            float4 b0 = *(const float4*)(WbS + (k4 + 0) * 64 + (tx << 2));
            float4 b1 = *(const float4*)(WbS + (k4 + 1) * 64 + (tx << 2));
            float4 b2 = *(const float4*)(WbS + (k4 + 2) * 64 + (tx << 2));
            float4 b3 = *(const float4*)(WbS + (k4 + 3) * 64 + (tx << 2));
#pragma unroll
            for (int i = 0; i < 4; i++) {
                am[i][0] += av[i].x * b0.x; am[i][1] += av[i].x * b0.y;
                am[i][2] += av[i].x * b0.z; am[i][3] += av[i].x * b0.w;
                am[i][0] += av[i].y * b1.x; am[i][1] += av[i].y * b1.y;
                am[i][2] += av[i].y * b1.z; am[i][3] += av[i].y * b1.w;
                am[i][0] += av[i].z * b2.x; am[i][1] += av[i].z * b2.y;
                am[i][2] += av[i].z * b2.z; am[i][3] += av[i].z * b2.w;
                am[i][0] += av[i].w * b3.x; am[i][1] += av[i].w * b3.y;
                am[i][2] += av[i].w * b3.z; am[i][3] += av[i].w * b3.w;
            }
        }

        float lp[4];
#pragma unroll
        for (int i = 0; i < 4; i++) {
            float t = 0.f;
#pragma unroll
            for (int j = 0; j < 4; j++) {
                float a = fmaxf(am[i][j] + bbS[(tx << 2) + j], 0.f);
                am[i][j] = a;
                t += a * WlS[(tx << 2) + j];
            }
            lp[i] = t;
        }
#pragma unroll
        for (int o = 8; o; o >>= 1)
#pragma unroll
            for (int i = 0; i < 4; i++) lp[i] += __shfl_xor_sync(0xffffffffu, lp[i], o);
        if (tx == 0) {
            const float blv = __ldg(&bl[0]);
#pragma unroll
            for (int i = 0; i < 4; i++)
                g_logits[(((b << 3) + g) << 10) + mbase + (ty << 2) + i] = lp[i] + blv;
        }
#pragma unroll
        for (int j = 0; j < 4; j++) {
            float ap = am[0][j] * mS[(ty << 2) + 0] + am[1][j] * mS[(ty << 2) + 1] +
                       am[2][j] * mS[(ty << 2) + 2] + am[3][j] * mS[(ty << 2) + 3];
            atomicAdd(&apS[(tx << 2) + j], ap);
        }
        __syncthreads();
        if (tid < 64)
            atomicAdd(&g_ampool[(((b << 3) + g) << 6) + tid], apS[tid]);
        __syncthreads();
    }
}

// ---------------- finalize ----------------
__global__ void final_kernel(const float* __restrict__ mask,
                             const float* __restrict__ Wl2,
                             const float* __restrict__ bl2,
                             float* __restrict__ out) {
    const int h = blockIdx.x, b = blockIdx.y;
    const int tid = threadIdx.x;
    const int lane = tid & 31, wrp = tid >> 5;
    __shared__ float wsm[1024];
    __shared__ float redA[8], redB[8], bc[4];
    __shared__ float pm[64], ac[128], psm[256];

    const float* lg = g_logits + (((size_t)b * 8 + h) << 10);
    const float* mrow = mask + ((size_t)b << 10);

    float l[4], mk[4];
    float lmax = -1e30f, msum = 0.f;
#pragma unroll
    for (int k = 0; k < 4; k++) {
        int m = tid + (k << 8);
        mk[k] = mrow[m];
        l[k] = (mk[k] == 0.f) ? -1e9f : lg[m];
        lmax = fmaxf(lmax, l[k]);
        msum += mk[k];
    }
#pragma unroll
    for (int o = 16; o; o >>= 1) {
        lmax = fmaxf(lmax, __shfl_xor_sync(0xffffffffu, lmax, o));
        msum += __shfl_xor_sync(0xffffffffu, msum, o);
    }
    if (lane == 0) { redA[wrp] = lmax; redB[wrp] = msum; }
    __syncthreads();
    if (tid == 0) {
        float a = -1e30f, s = 0.f;
#pragma unroll
        for (int i = 0; i < 8; i++) { a = fmaxf(a, redA[i]); s += redB[i]; }
        bc[0] = a; bc[1] = s;
    }
    __syncthreads();
    const float gmax = bc[0], msumv = bc[1];

    float es = 0.f;
#pragma unroll
    for (int k = 0; k < 4; k++) {
        float e = __expf(l[k] - gmax);
        wsm[tid + (k << 8)] = e;
        es += e;
    }
#pragma unroll
    for (int o = 16; o; o >>= 1) es += __shfl_xor_sync(0xffffffffu, es, o);
    if (lane == 0) redA[wrp] = es;
    __syncthreads();
    if (tid == 0) {
        float s = 0.f;
#pragma unroll
        for (int i = 0; i < 8; i++) s += redA[i];
        bc[2] = s;
    }
    if (tid < 64) pm[tid] = g_ampool[(((b << 3) + h) << 6) + tid] / msumv;
    __syncthreads();
    const float inv = 1.f / bc[2];

    if (tid < 128) {
        float t = bl2[tid];
#pragma unroll 8
        for (int n = 0; n < 64; n++) t += pm[n] * Wl2[n * 128 + tid];
        ac[tid] = 1.f / (1.f + __expf(-t));
    }
    __syncthreads();

    const int s2 = tid >> 7, d = tid & 127;
    const float* v2p = g_v2 + ((size_t)(b << 10)) * 1024 + (h << 7) + d;
    float accp = 0.f;
    for (int m = s2; m < 1024; m += 8) {
        accp += wsm[m] * v2p[(size_t)m * 1024];
        accp += wsm[m + 2] * v2p[(size_t)(m + 2) * 1024];
        accp += wsm[m + 4] * v2p[(size_t)(m + 4) * 1024];
        accp += wsm[m + 6] * v2p[(size_t)(m + 6) * 1024];
    }
    psm[tid] = accp;
    __syncthreads();
    if (tid < 128) {
        float p = (psm[tid] + psm[tid + 128]) * inv;
        int oi = (b << 10) + (h << 7) + tid;
        out[oi] = g_v1gn[oi] * p * ac[tid];
    }
}

// ---------------- launch ----------------
extern "C" void kernel_launch(void* const* d_in, const int* in_sizes, int n_in,
                              void* d_out, int out_size) {
    const float* query  = (const float*)d_in[0];
    const float* key    = (const float*)d_in[1];
    const float* mask   = (const float*)d_in[2];
    const float* value1 = (const float*)d_in[3];
    const float* value2 = (const float*)d_in[4];
    const float* Wq  = (const float*)d_in[5];
    const float* bq  = (const float*)d_in[6];
    const float* gq  = (const float*)d_in[7];
    const float* gbq = (const float*)d_in[8];
    const float* Wk  = (const float*)d_in[9];
    const float* bk  = (const float*)d_in[10];
    const float* gk  = (const float*)d_in[11];
    const float* gbk = (const float*)d_in[12];
    const float* Wv1  = (const float*)d_in[13];
    const float* bv1  = (const float*)d_in[14];
    const float* gv1  = (const float*)d_in[15];
    const float* gbv1 = (const float*)d_in[16];
    const float* Wv2  = (const float*)d_in[17];
    const float* bv2  = (const float*)d_in[18];
    const float* gv2  = (const float*)d_in[19];
    const float* gbv2 = (const float*)d_in[20];
    const float* Wb  = (const float*)d_in[21];
    const float* bb  = (const float*)d_in[22];
    const float* Wl  = (const float*)d_in[23];
    const float* bl  = (const float*)d_in[24];
    const float* Wl2 = (const float*)d_in[25];
    const float* bl2 = (const float*)d_in[26];
    float* out = (float*)d_out;

    cudaFuncSetAttribute(gemm_kernel<true>,  cudaFuncAttributeMaxDynamicSharedMemorySize,
                         SM_GEMM_TOTAL);
    cudaFuncSetAttribute(gemm_kernel<false>, cudaFuncAttributeMaxDynamicSharedMemorySize,
                         SM_GEMM_TOTAL);

    zero_kernel<<<512, 256>>>();
    small_partial<<<dim3(8, 4, 2), 256>>>(query, value1, Wq, Wv1);
    small_finalize<<<128, 256>>>(bq, gq, gbq, bv1, gv1, gbv1);
    gemm_kernel<true><<<4096, 256, SM_GEMM_TOTAL>>>(key, Wk, bk, gk, gbk);
    gemm_kernel<false><<<4096, 256, SM_GEMM_TOTAL>>>(value2, Wv2, bv2, gv2, gbv2);
    attn_kernel<<<1024, 256>>>(Wb, bb, Wl, bl, mask);
    final_kernel<<<dim3(8, 64), 256>>>(mask, Wl2, bl2, out);
}